// round 15
// baseline (speedup 1.0000x reference)
#include <cuda_runtime.h>
#include <cuda_bf16.h>
#include <math.h>
#include <stdint.h>

// Sigma_out[b][i][l] = p_i * p_l * ( S[i][l] - q[i] - r[l] + s )
//   p = softmax(mu[b]) ; q = S p ; r = p^T S ; s = p^T S p
//
// Two kernels + PDL overlap:
//   kernel 1: softmax (warp-per-row, shuffle-only) -> mu_out; triggers
//             programmatic completion right after its stores.
//   kernel 2: launched with ProgrammaticStreamSerialization; issues its
//             PF=24 Sigma prefetch FIRST, then cudaGridDependencySynchronize()
//             before reading p -> softmax kernel + launch gap hide under the
//             prefetch ramp of the first wave.
// kernel 2 internals = round-14 winner (167.9us @ 77% DRAM): fused r in
// staging, LDS.128 q-pass, 16B-block swizzle, register retention, scalar
// 32-bit global accesses.

#define C 128
#define THREADS 256
#define EPT 64
#define PF 24

// ---------------- kernel 1: softmax, one warp per row --------------------
__global__ __launch_bounds__(256) void softmax_rows_kernel(
    const float* __restrict__ mu,   // [B, C]
    float* __restrict__ mu_out,     // [B, C]
    int B)
{
    const int warp = (blockIdx.x * blockDim.x + threadIdx.x) >> 5;
    const int lane = threadIdx.x & 31;
    if (warp < B) {
        const float* row = mu + (size_t)warp * C;
        float x0 = row[lane], x1 = row[lane + 32], x2 = row[lane + 64], x3 = row[lane + 96];

        float m = fmaxf(fmaxf(x0, x1), fmaxf(x2, x3));
        #pragma unroll
        for (int o = 16; o > 0; o >>= 1)
            m = fmaxf(m, __shfl_xor_sync(0xffffffffu, m, o));

        float e0 = expf(x0 - m), e1 = expf(x1 - m), e2 = expf(x2 - m), e3 = expf(x3 - m);
        float ssum = e0 + e1 + e2 + e3;
        #pragma unroll
        for (int o = 16; o > 0; o >>= 1)
            ssum += __shfl_xor_sync(0xffffffffu, ssum, o);
        float inv = 1.0f / ssum;

        float* orow = mu_out + (size_t)warp * C;
        orow[lane]      = e0 * inv;
        orow[lane + 32] = e1 * inv;
        orow[lane + 64] = e2 * inv;
        orow[lane + 96] = e3 * inv;
    }
    // signal dependents: all p values for this block are written
    cudaTriggerProgrammaticLaunchCompletion();
}

// ---------------- kernel 2: Sigma transform ------------------------------
__global__ __launch_bounds__(THREADS, 2) void sigma_kernel(
    const float* __restrict__ p_in,     // [B, C] = softmax(mu)
    const float* __restrict__ Sigma,    // [B, C, C]
    float* __restrict__ sig_out)        // [B, C, C]
{
    const int b  = blockIdx.x;
    const int t  = threadIdx.x;
    const int k  = t & (C - 1);
    const int c  = t >> 7;
    const int kb = k >> 2;
    const int ko = k & 3;

    extern __shared__ __align__(16) float sm[];
    float* Ssm   = sm;                  // 16384, block-swizzled
    float* psh   = sm + C * C;          // 128
    float* pq    = psh + C;             // 128
    float* rtmp  = pq + C;              // 256
    float* qpart = rtmp + 2 * C;        // 256
    float* red   = qpart + 2 * C;       // 16

    const float* g = Sigma + (size_t)b * (C * C) + t;

    // ---- deep prefetch (independent of kernel 1's output)
    float pfv[PF];
    #pragma unroll
    for (int j = 0; j < PF; ++j) pfv[j] = g[THREADS * j];

    // ---- wait for the softmax grid, then load p
    cudaGridDependencySynchronize();
    if (t < C) psh[t] = p_in[b * C + t];
    __syncthreads();

    // ---- staging + fused r accumulation (rows i = c, c+2, ...)
    {
        float racc = 0.0f;
        int i = c;
        #pragma unroll
        for (int j = 0; j < EPT; ++j) {
            float val = (j < PF) ? pfv[j] : g[THREADS * j];
            Ssm[i * C + (((kb ^ (i & 31)) << 2) | ko)] = val;
            racc = fmaf(val, psh[i], racc);
            i += 2;
        }
        rtmp[t] = racc;   // r[k] = rtmp[k] + rtmp[k+128]
    }
    __syncthreads();

    // ---- q pass, vectorized: thread t -> row iq = t&127, half c
    {
        const int iq = k;
        const int sw = iq & 31;
        const float4* row4 = reinterpret_cast<const float4*>(Ssm + iq * C);
        const float4* p4   = reinterpret_cast<const float4*>(psh);
        float acc = 0.0f;
        #pragma unroll
        for (int bb = 0; bb < 16; ++bb) {
            const int blk = 16 * c + bb;           // warp-uniform
            float4 vv = row4[blk ^ sw];
            float4 pp = p4[blk];
            acc = fmaf(vv.x, pp.x, acc);
            acc = fmaf(vv.y, pp.y, acc);
            acc = fmaf(vv.z, pp.z, acc);
            acc = fmaf(vv.w, pp.w, acc);
        }
        qpart[t] = acc;   // q[i] = qpart[i] + qpart[i+128]
    }
    __syncthreads();

    // ---- s = p . q ; pq[i] = p_i*(q_i - s)
    float qi = (t < C) ? (qpart[t] + qpart[t + C]) : 0.0f;
    float sv = (t < C) ? psh[t] * qi : 0.0f;
    #pragma unroll
    for (int o = 16; o > 0; o >>= 1)
        sv += __shfl_xor_sync(0xffffffffu, sv, o);
    if (t < C && (t & 31) == 0) red[t >> 5] = sv;
    __syncthreads();
    const float s = red[0] + red[1] + red[2] + red[3];
    if (t < C) pq[t] = psh[t] * (qi - s);
    __syncthreads();

    // ---- output: out[i][k] = p_k * ( p_i*(S[i][k] - r_k) - pq[i] )
    {
        const float pk = psh[k];
        const float rk = rtmp[k] + rtmp[k + C];
        float* o = sig_out + (size_t)b * (C * C) + t;
        int i = c;
        #pragma unroll
        for (int j = 0; j < EPT; ++j) {
            float val = (j < PF) ? pfv[j]
                                 : Ssm[i * C + (((kb ^ (i & 31)) << 2) | ko)];
            o[THREADS * j] = pk * (psh[i] * (val - rk) - pq[i]);
            i += 2;
        }
    }
}

extern "C" void kernel_launch(void* const* d_in, const int* in_sizes, int n_in,
                              void* d_out, int out_size)
{
    // Identify inputs by size: Sigma is C times larger than mu.
    const float* in0 = (const float*)d_in[0];
    const float* in1 = (const float*)d_in[1];
    const float* mu;
    const float* Sigma;
    int B;
    if (in_sizes[0] <= in_sizes[1]) {
        mu = in0; Sigma = in1; B = in_sizes[0] / C;
    } else {
        mu = in1; Sigma = in0; B = in_sizes[1] / C;
    }

    float* mu_out  = (float*)d_out;               // first B*C elements
    float* sig_out = (float*)d_out + (size_t)B * C;

    // kernel 1: 8 rows per 256-thread block
    int blocks1 = (B + 7) / 8;
    softmax_rows_kernel<<<blocks1, 256>>>(mu, mu_out, B);

    // kernel 2: one CTA per batch, PDL-overlapped with kernel 1
    const int smem = (C * C + 2 * C + 2 * (2 * C) + 16) * sizeof(float);
    cudaFuncSetAttribute(sigma_kernel,
                         cudaFuncAttributeMaxDynamicSharedMemorySize, smem);

    cudaLaunchConfig_t cfg = {};
    cfg.gridDim  = dim3((unsigned)B);
    cfg.blockDim = dim3(THREADS);
    cfg.dynamicSmemBytes = smem;
    cudaLaunchAttribute attrs[1];
    attrs[0].id = cudaLaunchAttributeProgrammaticStreamSerialization;
    attrs[0].val.programmaticStreamSerializationAllowed = 1;
    cfg.attrs = attrs;
    cfg.numAttrs = 1;
    cudaLaunchKernelEx(&cfg, sigma_kernel, (const float*)mu_out,
                       (const float*)Sigma, (float*)sig_out);
}

// round 16
// speedup vs baseline: 1.0309x; 1.0309x over previous
#include <cuda_runtime.h>
#include <cuda_bf16.h>
#include <math.h>
#include <stdint.h>

// Sigma_out[b][i][l] = p_i * p_l * ( S[i][l] - q[i] - r[l] + s )
//   p = softmax(mu[b]) ; q = S p ; r = p^T S ; s = p^T S p
//
// Two plain kernels (PDL reverted: neutral).
// kernel 2 = r14 winner + parity-packed broadcast tables:
//   staging p[i] broadcasts  : float4 from peo  (1 per 4 iterations)
//   output p[i]/pq[i] bcasts : float4 from prq  (1 per 2 iterations)
// cutting ~1150 l1tex wavefronts/CTA. Everything else unchanged:
// PF=24 register prefetch+retention, fused r in staging, LDS.128 q-pass,
// 16B-block swizzle, scalar 32-bit global accesses.

#define C 128
#define THREADS 256
#define EPT 64
#define PF 24

// ---------------- kernel 1: softmax, one warp per row --------------------
__global__ __launch_bounds__(256) void softmax_rows_kernel(
    const float* __restrict__ mu,   // [B, C]
    float* __restrict__ mu_out,     // [B, C]
    int B)
{
    const int warp = (blockIdx.x * blockDim.x + threadIdx.x) >> 5;
    const int lane = threadIdx.x & 31;
    if (warp >= B) return;

    const float* row = mu + (size_t)warp * C;
    float x0 = row[lane], x1 = row[lane + 32], x2 = row[lane + 64], x3 = row[lane + 96];

    float m = fmaxf(fmaxf(x0, x1), fmaxf(x2, x3));
    #pragma unroll
    for (int o = 16; o > 0; o >>= 1)
        m = fmaxf(m, __shfl_xor_sync(0xffffffffu, m, o));

    float e0 = expf(x0 - m), e1 = expf(x1 - m), e2 = expf(x2 - m), e3 = expf(x3 - m);
    float ssum = e0 + e1 + e2 + e3;
    #pragma unroll
    for (int o = 16; o > 0; o >>= 1)
        ssum += __shfl_xor_sync(0xffffffffu, ssum, o);
    float inv = 1.0f / ssum;

    float* orow = mu_out + (size_t)warp * C;
    orow[lane]      = e0 * inv;
    orow[lane + 32] = e1 * inv;
    orow[lane + 64] = e2 * inv;
    orow[lane + 96] = e3 * inv;
}

// ---------------- kernel 2: Sigma transform ------------------------------
__global__ __launch_bounds__(THREADS, 2) void sigma_kernel(
    const float* __restrict__ p_in,     // [B, C] = softmax(mu)
    const float* __restrict__ Sigma,    // [B, C, C]
    float* __restrict__ sig_out)        // [B, C, C]
{
    const int b  = blockIdx.x;
    const int t  = threadIdx.x;
    const int k  = t & (C - 1);
    const int c  = t >> 7;
    const int kb = k >> 2;
    const int ko = k & 3;

    extern __shared__ __align__(16) float sm[];
    float* Ssm   = sm;                  // 16384, block-swizzled
    float* psh   = sm + C * C;          // 128  (natural order, for q-pass)
    float* peo   = psh + C;             // 128  peo[c*64+j] = p[c+2j]
    float* prq   = peo + C;             // 256  float2: {p[c+2j], pq[c+2j]}
    float* rtmp  = prq + 2 * C;         // 256
    float* qpart = rtmp + 2 * C;        // 256
    float* red   = qpart + 2 * C;       // 16

    const float* g = Sigma + (size_t)b * (C * C) + t;

    // ---- deep prefetch, retained in registers through the whole kernel
    float pfv[PF];
    #pragma unroll
    for (int j = 0; j < PF; ++j) pfv[j] = g[THREADS * j];

    // ---- load p; build parity-packed table for staging broadcasts
    if (t < C) {
        float pt = p_in[b * C + t];
        psh[t] = pt;
        peo[(t & 1) * 64 + (t >> 1)] = pt;
    }
    __syncthreads();

    // ---- staging + fused r accumulation (rows i = c, c+2, ...)
    {
        const float4* pcol = reinterpret_cast<const float4*>(peo + c * 64);
        float racc = 0.0f;
        int i = c;
        #pragma unroll
        for (int j4 = 0; j4 < 16; ++j4) {
            const float4 pp = pcol[j4];          // p for i = c+2(4j4+0..3)
            #pragma unroll
            for (int u = 0; u < 4; ++u) {
                const int j = 4 * j4 + u;
                float val = (j < PF) ? pfv[j] : g[THREADS * j];
                Ssm[i * C + (((kb ^ (i & 31)) << 2) | ko)] = val;
                float pi = (u == 0) ? pp.x : (u == 1) ? pp.y : (u == 2) ? pp.z : pp.w;
                racc = fmaf(val, pi, racc);
                i += 2;
            }
        }
        rtmp[t] = racc;   // r[k] = rtmp[k] + rtmp[k+128]
    }
    __syncthreads();

    // ---- q pass, vectorized: thread t -> row iq = t&127, half c
    {
        const int iq = k;
        const int sw = iq & 31;
        const float4* row4 = reinterpret_cast<const float4*>(Ssm + iq * C);
        const float4* p4   = reinterpret_cast<const float4*>(psh);
        float acc = 0.0f;
        #pragma unroll
        for (int bb = 0; bb < 16; ++bb) {
            const int blk = 16 * c + bb;           // warp-uniform
            float4 vv = row4[blk ^ sw];
            float4 pp = p4[blk];
            acc = fmaf(vv.x, pp.x, acc);
            acc = fmaf(vv.y, pp.y, acc);
            acc = fmaf(vv.z, pp.z, acc);
            acc = fmaf(vv.w, pp.w, acc);
        }
        qpart[t] = acc;   // q[i] = qpart[i] + qpart[i+128]
    }
    __syncthreads();

    // ---- s = p . q ; pack {p_i, p_i*(q_i - s)} parity-split
    float qi = (t < C) ? (qpart[t] + qpart[t + C]) : 0.0f;
    float sv = (t < C) ? psh[t] * qi : 0.0f;
    #pragma unroll
    for (int o = 16; o > 0; o >>= 1)
        sv += __shfl_xor_sync(0xffffffffu, sv, o);
    if (t < C && (t & 31) == 0) red[t >> 5] = sv;
    __syncthreads();
    const float s = red[0] + red[1] + red[2] + red[3];
    if (t < C) {
        float pt = psh[t];
        reinterpret_cast<float2*>(prq)[(t & 1) * 64 + (t >> 1)] =
            make_float2(pt, pt * (qi - s));
    }
    __syncthreads();

    // ---- output: out[i][k] = p_k * ( p_i*(S[i][k] - r_k) - pq[i] )
    {
        const float pk = psh[k];
        const float rk = rtmp[k] + rtmp[k + C];
        const float4* prc = reinterpret_cast<const float4*>(prq + c * 128);
        float* o = sig_out + (size_t)b * (C * C) + t;
        int i = c;
        #pragma unroll
        for (int j2 = 0; j2 < 32; ++j2) {
            const float4 pr = prc[j2];   // {p[i], pq[i], p[i+2], pq[i+2]}
            {
                const int j = 2 * j2;
                float val = (j < PF) ? pfv[j]
                                     : Ssm[i * C + (((kb ^ (i & 31)) << 2) | ko)];
                o[THREADS * j] = pk * (pr.x * (val - rk) - pr.y);
                i += 2;
            }
            {
                const int j = 2 * j2 + 1;
                float val = (j < PF) ? pfv[j]
                                     : Ssm[i * C + (((kb ^ (i & 31)) << 2) | ko)];
                o[THREADS * j] = pk * (pr.z * (val - rk) - pr.w);
                i += 2;
            }
        }
    }
}

extern "C" void kernel_launch(void* const* d_in, const int* in_sizes, int n_in,
                              void* d_out, int out_size)
{
    // Identify inputs by size: Sigma is C times larger than mu.
    const float* in0 = (const float*)d_in[0];
    const float* in1 = (const float*)d_in[1];
    const float* mu;
    const float* Sigma;
    int B;
    if (in_sizes[0] <= in_sizes[1]) {
        mu = in0; Sigma = in1; B = in_sizes[0] / C;
    } else {
        mu = in1; Sigma = in0; B = in_sizes[1] / C;
    }

    float* mu_out  = (float*)d_out;               // first B*C elements
    float* sig_out = (float*)d_out + (size_t)B * C;

    // kernel 1: 8 rows per 256-thread block
    int blocks1 = (B + 7) / 8;
    softmax_rows_kernel<<<blocks1, 256>>>(mu, mu_out, B);

    // kernel 2: one CTA per batch
    const int smem = (C * C + C + C + 2 * C + 2 * C + 2 * C + 16) * sizeof(float);
    cudaFuncSetAttribute(sigma_kernel,
                         cudaFuncAttributeMaxDynamicSharedMemorySize, smem);
    sigma_kernel<<<B, THREADS, smem>>>(mu_out, Sigma, sig_out);
}